// round 9
// baseline (speedup 1.0000x reference)
#include <cuda_runtime.h>
#include <cstdint>

#define NNODES 50000
#define OUTD   128

// ---------------- device scratch (no allocations allowed) ----------------
__device__ float4 g_S4[NNODES * (OUTD / 4)];   // 25.6 MB accumulator S[N][128]
__device__ float  g_cnt[NNODES];               // per-node edge count (as float)
__device__ float4 g_Wp4[OUTD * OUTD / 4];      // Wc=W2@W1, k-paired [k2][o][2];
                                               // float4 type => 16B aligned
__device__ float  g_bc[OUTD];                  // W2 @ b1

// ---------------- f32x2 packed-FMA helpers -------------------------------
__device__ __forceinline__ void unpack2(unsigned long long v, float& x, float& y) {
    asm("mov.b64 {%0, %1}, %2;" : "=f"(x), "=f"(y) : "l"(v));
}
__device__ __forceinline__ void ffma2(unsigned long long& d,
                                      unsigned long long a,
                                      unsigned long long b) {
    asm("fma.rn.f32x2 %0, %1, %2, %0;" : "+l"(d) : "l"(a), "l"(b));
}
__device__ __forceinline__ void red4(float* dst, float4 v) {
    asm volatile("red.global.add.v4.f32 [%0], {%1, %2, %3, %4};"
                 :: "l"(dst), "f"(v.x), "f"(v.y), "f"(v.z), "f"(v.w)
                 : "memory");
}

// ---------------- prep: Wc = W2 @ W1 (k-paired store), bc = W2 @ b1 ------
// Same kernels that passed in R1/R5/R6; only wct's store line changed.
__global__ void wct_kernel(const float* __restrict__ W1,   // [512, 128]
                           const float* __restrict__ W2) { // [128, 512]
    int o = blockIdx.x;
    int k = threadIdx.x;
    const float* w2row = W2 + (size_t)o * 512;
    float acc = 0.f;
    #pragma unroll 8
    for (int h = 0; h < 512; ++h)
        acc += w2row[h] * W1[(size_t)h * OUTD + k];
    // k-paired layout: float index (k/2)*256 + o*2 + (k&1)
    ((float*)g_Wp4)[(k >> 1) * 256 + o * 2 + (k & 1)] = acc;
}

__global__ void bc_kernel(const float* __restrict__ W2, const float* __restrict__ b1) {
    int o = threadIdx.x;
    float acc = 0.f;
    #pragma unroll 8
    for (int h = 0; h < 512; ++h)
        acc += W2[(size_t)o * 512 + h] * b1[h];
    g_bc[o] = acc;
}

// ---------------- zero accumulators (required every graph replay) --------
__global__ void zero_kernel() {
    int i = blockIdx.x * blockDim.x + threadIdx.x;
    int stride = gridDim.x * blockDim.x;
    const int n4 = NNODES * (OUTD / 4);
    for (int j = i; j < n4; j += stride) g_S4[j] = make_float4(0.f, 0.f, 0.f, 0.f);
    for (int j = i; j < NNODES; j += stride) g_cnt[j] = 0.f;
}

// ---------------- scatter: S[index[e]] += msg[e]; cnt[index[e]] += 1 -----
// Warp per edge; LTS-transport bound; measured 94.6/95.4us. Verbatim.
__global__ void scatter_kernel(const float4* __restrict__ msg4,
                               const int* __restrict__ index, int E) {
    int lane  = threadIdx.x & 31;
    int warp  = (blockIdx.x * blockDim.x + threadIdx.x) >> 5;
    int nwarp = (gridDim.x * blockDim.x) >> 5;

    int e = warp;
    for (; e + 3 * nwarp < E; e += 4 * nwarp) {
        int e0 = e, e1 = e + nwarp, e2 = e + 2 * nwarp, e3 = e + 3 * nwarp;
        int n0 = __ldg(index + e0);
        int n1 = __ldg(index + e1);
        int n2 = __ldg(index + e2);
        int n3 = __ldg(index + e3);
        float4 v0 = __ldg(msg4 + (size_t)e0 * 32 + lane);
        float4 v1 = __ldg(msg4 + (size_t)e1 * 32 + lane);
        float4 v2 = __ldg(msg4 + (size_t)e2 * 32 + lane);
        float4 v3 = __ldg(msg4 + (size_t)e3 * 32 + lane);
        red4((float*)&g_S4[(size_t)n0 * 32 + lane], v0);
        red4((float*)&g_S4[(size_t)n1 * 32 + lane], v1);
        red4((float*)&g_S4[(size_t)n2 * 32 + lane], v2);
        red4((float*)&g_S4[(size_t)n3 * 32 + lane], v3);
        if (lane == 0) {
            atomicAdd(&g_cnt[n0], 1.0f);
            atomicAdd(&g_cnt[n1], 1.0f);
            atomicAdd(&g_cnt[n2], 1.0f);
            atomicAdd(&g_cnt[n3], 1.0f);
        }
    }
    for (; e < E; e += nwarp) {
        int n = __ldg(index + e);
        float4 v = __ldg(msg4 + (size_t)e * 32 + lane);
        red4((float*)&g_S4[(size_t)n * 32 + lane], v);
        if (lane == 0) atomicAdd(&g_cnt[n], 1.0f);
    }
}

// ---------------- final: out = leaky(S @ WcT + cnt*bc + b2) --------------
// 64 nodes/block, 256 threads, 33.8 KB static smem.
// S tile row-major [64][132] (rows 528 B -> LDS.64 8B-aligned, broadcast).
// W via __ldg LDG.128 from g_Wp4 (16B-aligned by type; 64 KB, L1-resident).
// k-paired f32x2: each FFMA2 folds two k's; no register packing in the loop.
// Thread tile: 2 rows x 8 cols, two column passes.
__global__ void __launch_bounds__(256) final_kernel(const float* __restrict__ b2,
                                                    float* __restrict__ out, int N) {
    __shared__ float sS[64 * 132];     // 33792 B

    const int t    = threadIdx.x;
    const int row0 = blockIdx.x * 64;

    // load S tile: 8 independent coalesced float4 loads per thread (MLP=8)
    #pragma unroll
    for (int j = 0; j < 8; ++j) {
        int f = t + 256 * j;
        int r = f >> 5;                // row within tile (const per warp)
        int c4 = f & 31;               // float4 column
        int n = row0 + r;
        float4 v = make_float4(0.f, 0.f, 0.f, 0.f);
        if (n < N) v = __ldg(&g_S4[(size_t)n * 32 + c4]);
        *(float4*)(sS + r * 132 + c4 * 4) = v;   // 528*r + 16*c4: 16B aligned
    }
    __syncthreads();

    const int tx = t & 7;              // col group: 8 cols
    const int ty = t >> 3;             // row group: 2 rows
    const int rA = 2 * ty;
    const int rB = 2 * ty + 1;
    const int nA = row0 + rA;
    const int nB = row0 + rB;
    const float cntA = (nA < N) ? g_cnt[nA] : 0.f;
    const float cntB = (nB < N) ? g_cnt[nB] : 0.f;

    #pragma unroll 1
    for (int p = 0; p < 2; ++p) {
        const int c0 = p * 64 + tx * 8;            // 8 output cols (c0 even)
        const float4* Wp4 = g_Wp4 + (c0 >> 1);     // 16 floats = 4 float4 / k2

        unsigned long long aA[8], aB[8];
        #pragma unroll
        for (int j = 0; j < 8; ++j) { aA[j] = 0ull; aB[j] = 0ull; }

        #pragma unroll 4
        for (int k2 = 0; k2 < 64; ++k2) {
            float4 w0 = __ldg(Wp4 + (size_t)k2 * 64 + 0);
            float4 w1 = __ldg(Wp4 + (size_t)k2 * 64 + 1);
            float4 w2 = __ldg(Wp4 + (size_t)k2 * 64 + 2);
            float4 w3 = __ldg(Wp4 + (size_t)k2 * 64 + 3);
            unsigned long long sA = *(const unsigned long long*)(sS + rA * 132 + 2 * k2);
            unsigned long long sB = *(const unsigned long long*)(sS + rB * 132 + 2 * k2);
            const unsigned long long* wq = (const unsigned long long*)&w0;
            ffma2(aA[0], sA, wq[0]); ffma2(aA[1], sA, wq[1]);
            ffma2(aB[0], sB, wq[0]); ffma2(aB[1], sB, wq[1]);
            wq = (const unsigned long long*)&w1;
            ffma2(aA[2], sA, wq[0]); ffma2(aA[3], sA, wq[1]);
            ffma2(aB[2], sB, wq[0]); ffma2(aB[3], sB, wq[1]);
            wq = (const unsigned long long*)&w2;
            ffma2(aA[4], sA, wq[0]); ffma2(aA[5], sA, wq[1]);
            ffma2(aB[4], sB, wq[0]); ffma2(aB[5], sB, wq[1]);
            wq = (const unsigned long long*)&w3;
            ffma2(aA[6], sA, wq[0]); ffma2(aA[7], sA, wq[1]);
            ffma2(aB[6], sB, wq[0]); ffma2(aB[7], sB, wq[1]);
        }

        // epilogue: fold k-pairs, + cnt*bc + b2, LeakyReLU(0.01), store
        float resA[8], resB[8];
        #pragma unroll
        for (int j = 0; j < 8; ++j) {
            int c = c0 + j;
            float bc = g_bc[c];
            float bb = __ldg(b2 + c);
            float lo, hi;
            unpack2(aA[j], lo, hi);
            float vA = lo + hi + cntA * bc + bb;
            unpack2(aB[j], lo, hi);
            float vB = lo + hi + cntB * bc + bb;
            resA[j] = (vA >= 0.f) ? vA : 0.01f * vA;
            resB[j] = (vB >= 0.f) ? vB : 0.01f * vB;
        }
        if (nA < N) {
            float4* o4 = (float4*)(out + (size_t)nA * OUTD + c0);
            o4[0] = make_float4(resA[0], resA[1], resA[2], resA[3]);
            o4[1] = make_float4(resA[4], resA[5], resA[6], resA[7]);
        }
        if (nB < N) {
            float4* o4 = (float4*)(out + (size_t)nB * OUTD + c0);
            o4[0] = make_float4(resB[0], resB[1], resB[2], resB[3]);
            o4[1] = make_float4(resB[4], resB[5], resB[6], resB[7]);
        }
    }
}

// ---------------- launch: pure kernel launches, no API calls -------------
extern "C" void kernel_launch(void* const* d_in, const int* in_sizes, int n_in,
                              void* d_out, int out_size) {
    // metadata order: msg, x_i, x_j, e_ij, index, num_nodes, W1, b1, W2, b2
    const float* msg   = (const float*)d_in[0];
    const int*   index = (const int*)  d_in[4];
    const float* W1    = (const float*)d_in[6];
    const float* b1    = (const float*)d_in[7];
    const float* W2    = (const float*)d_in[8];
    const float* b2    = (const float*)d_in[9];
    float* out = (float*)d_out;

    int E = in_sizes[4];
    int N = out_size / OUTD;
    if (N > NNODES) N = NNODES;

    wct_kernel<<<OUTD, OUTD>>>(W1, W2);
    bc_kernel<<<1, OUTD>>>(W2, b1);
    zero_kernel<<<2048, 256>>>();
    scatter_kernel<<<12500, 256>>>((const float4*)msg, index, E);
    final_kernel<<<(N + 63) / 64, 256>>>(b2, out, N);
}

// round 10
// speedup vs baseline: 1.5368x; 1.5368x over previous
#include <cuda_runtime.h>
#include <cstdint>

#define NNODES 50000
#define OUTD   128

// ---------------- device scratch (no allocations allowed) ----------------
__device__ float4 g_S4[NNODES * (OUTD / 4)];   // 25.6 MB accumulator S[N][128]
__device__ float  g_cnt[NNODES];               // per-node edge count (as float)
__device__ float4 g_Wp4[OUTD * OUTD / 4];      // Wc k-paired [k2][o][2]; 16B-aligned type
__device__ float  g_bc[OUTD];                  // W2 @ b1

// ---------------- f32x2 helpers ------------------------------------------
__device__ __forceinline__ void unpack2(unsigned long long v, float& x, float& y) {
    asm("mov.b64 {%0, %1}, %2;" : "=f"(x), "=f"(y) : "l"(v));
}
__device__ __forceinline__ void ffma2(unsigned long long& d,
                                      unsigned long long a,
                                      unsigned long long b) {
    asm("fma.rn.f32x2 %0, %1, %2, %0;" : "+l"(d) : "l"(a), "l"(b));
}
__device__ __forceinline__ void red4(float* dst, float4 v) {
    asm volatile("red.global.add.v4.f32 [%0], {%1, %2, %3, %4};"
                 :: "l"(dst), "f"(v.x), "f"(v.y), "f"(v.z), "f"(v.w)
                 : "memory");
}

// ---------------- prep: Wc = W2@W1 (k-paired) AND bc = W2@b1 -------------
// One block per output row o; 128 threads. bc folded in (no 1-block kernel).
__global__ void wct_kernel(const float* __restrict__ W1,   // [512, 128]
                           const float* __restrict__ W2,   // [128, 512]
                           const float* __restrict__ b1) {
    __shared__ float sb[128];
    const int o = blockIdx.x;
    const int k = threadIdx.x;
    const float* w2row = W2 + (size_t)o * 512;

    // bc partial: thread k covers h = k, k+128, k+256, k+384
    sb[k] = w2row[k] * __ldg(&b1[k])
          + w2row[k + 128] * __ldg(&b1[k + 128])
          + w2row[k + 256] * __ldg(&b1[k + 256])
          + w2row[k + 384] * __ldg(&b1[k + 384]);

    float acc = 0.f;
    #pragma unroll 8
    for (int h = 0; h < 512; ++h)
        acc += w2row[h] * W1[(size_t)h * OUTD + k];
    // k-paired store: float index (k/2)*256 + o*2 + (k&1)
    ((float*)g_Wp4)[(k >> 1) * 256 + o * 2 + (k & 1)] = acc;

    __syncthreads();
    if (k < 32) {
        float s = sb[k] + sb[k + 32] + sb[k + 64] + sb[k + 96];
        #pragma unroll
        for (int d = 16; d > 0; d >>= 1)
            s += __shfl_down_sync(0xffffffffu, s, d);
        if (k == 0) g_bc[o] = s;
    }
}

// ---------------- zero accumulators (required every graph replay) --------
__global__ void zero_kernel() {
    int i = blockIdx.x * blockDim.x + threadIdx.x;
    int stride = gridDim.x * blockDim.x;
    const int n4 = NNODES * (OUTD / 4);
    for (int j = i; j < n4; j += stride) g_S4[j] = make_float4(0.f, 0.f, 0.f, 0.f);
    for (int j = i; j < NNODES; j += stride) g_cnt[j] = 0.f;
}

// ---------------- scatter: S[index[e]] += msg[e]; cnt += 1 ---------------
// Warp per edge; LTS-transport bound; 94.6-95.4us across 3 runs. Verbatim.
__global__ void scatter_kernel(const float4* __restrict__ msg4,
                               const int* __restrict__ index, int E) {
    int lane  = threadIdx.x & 31;
    int warp  = (blockIdx.x * blockDim.x + threadIdx.x) >> 5;
    int nwarp = (gridDim.x * blockDim.x) >> 5;

    int e = warp;
    for (; e + 3 * nwarp < E; e += 4 * nwarp) {
        int e0 = e, e1 = e + nwarp, e2 = e + 2 * nwarp, e3 = e + 3 * nwarp;
        int n0 = __ldg(index + e0);
        int n1 = __ldg(index + e1);
        int n2 = __ldg(index + e2);
        int n3 = __ldg(index + e3);
        float4 v0 = __ldg(msg4 + (size_t)e0 * 32 + lane);
        float4 v1 = __ldg(msg4 + (size_t)e1 * 32 + lane);
        float4 v2 = __ldg(msg4 + (size_t)e2 * 32 + lane);
        float4 v3 = __ldg(msg4 + (size_t)e3 * 32 + lane);
        red4((float*)&g_S4[(size_t)n0 * 32 + lane], v0);
        red4((float*)&g_S4[(size_t)n1 * 32 + lane], v1);
        red4((float*)&g_S4[(size_t)n2 * 32 + lane], v2);
        red4((float*)&g_S4[(size_t)n3 * 32 + lane], v3);
        if (lane == 0) {
            atomicAdd(&g_cnt[n0], 1.0f);
            atomicAdd(&g_cnt[n1], 1.0f);
            atomicAdd(&g_cnt[n2], 1.0f);
            atomicAdd(&g_cnt[n3], 1.0f);
        }
    }
    for (; e < E; e += nwarp) {
        int n = __ldg(index + e);
        float4 v = __ldg(msg4 + (size_t)e * 32 + lane);
        red4((float*)&g_S4[(size_t)n * 32 + lane], v);
        if (lane == 0) atomicAdd(&g_cnt[n], 1.0f);
    }
}

// ---------------- final: out = leaky(S @ WcT + cnt*bc + b2) --------------
// 64 nodes/block, 256 threads, exactly 48 KB static smem, bank-conflict-free.
//   sS[64][128]: pair k2 of row r stored at r*128 + 2*((k2+r)&63)  (rotation
//     swizzle -> 8 rows/warp read 8 distinct banks on broadcast LDS.64).
//   sW4[64][16]: k-paired W pass chunk (32 cols). Thread tx reads interleaved
//     units {tx,tx+4,tx+8,tx+12} -> each LDS.128 phase spans 64 B: conflict-free.
// Inner loop: 4 LDS.128 + 1 LDS.64 + 8 FFMA2, zero register packing.
__global__ void __launch_bounds__(256) final_kernel(const float* __restrict__ b2,
                                                    float* __restrict__ out, int N) {
    __shared__ float  sS[64 * 128];    // 32768 B
    __shared__ float4 sW4[64 * 16];    // 16384 B  (total 49152 = 48 KB)

    const int t    = threadIdx.x;
    const int row0 = blockIdx.x * 64;

    // ---- fill S tile, swizzled; 8 coalesced float4 loads per thread ----
    #pragma unroll
    for (int j = 0; j < 8; ++j) {
        int f = t + 256 * j;
        int r = f >> 5;                // row within tile (const per warp)
        int c4 = f & 31;               // source float4 column (pairs 2c4, 2c4+1)
        int n = row0 + r;
        float4 v = make_float4(0.f, 0.f, 0.f, 0.f);
        if (n < N) v = __ldg(&g_S4[(size_t)n * 32 + c4]);
        int p0 = (2 * c4 + r) & 63;
        int p1 = (2 * c4 + 1 + r) & 63;
        *(float2*)&sS[r * 128 + 2 * p0] = make_float2(v.x, v.y);  // even idx: 8B ok
        *(float2*)&sS[r * 128 + 2 * p1] = make_float2(v.z, v.w);
    }

    const int tx = t & 3;              // W float4 group
    const int rT = t >> 2;             // row 0..63 (one row per thread)
    const int n  = row0 + rT;
    const float cnt = (n < N) ? g_cnt[n] : 0.f;

    #pragma unroll 1
    for (int p = 0; p < 4; ++p) {      // 4 passes of 32 columns
        __syncthreads();               // fill done / prior pass reads done
        #pragma unroll
        for (int i = 0; i < 4; ++i) {  // stage 1024 float4 (16 KB)
            int f = t + 256 * i;
            int k2 = f >> 4, g4 = f & 15;
            sW4[f] = g_Wp4[k2 * 64 + p * 16 + g4];
        }
        __syncthreads();

        unsigned long long a[8];
        #pragma unroll
        for (int j = 0; j < 8; ++j) a[j] = 0ull;

        #pragma unroll 4
        for (int k2 = 0; k2 < 64; ++k2) {
            // interleaved W units: tx, tx+4, tx+8, tx+12 (each = 2 col-pairs)
            float4 w0 = sW4[k2 * 16 + tx];
            float4 w1 = sW4[k2 * 16 + tx + 4];
            float4 w2 = sW4[k2 * 16 + tx + 8];
            float4 w3 = sW4[k2 * 16 + tx + 12];
            unsigned long long s =
                *(const unsigned long long*)&sS[rT * 128 + 2 * ((k2 + rT) & 63)];
            const unsigned long long* q;
            q = (const unsigned long long*)&w0; ffma2(a[0], s, q[0]); ffma2(a[1], s, q[1]);
            q = (const unsigned long long*)&w1; ffma2(a[2], s, q[0]); ffma2(a[3], s, q[1]);
            q = (const unsigned long long*)&w2; ffma2(a[4], s, q[0]); ffma2(a[5], s, q[1]);
            q = (const unsigned long long*)&w3; ffma2(a[6], s, q[0]); ffma2(a[7], s, q[1]);
        }

        // epilogue: thread's cols are pairs {2(tx+4q), 2(tx+4q)+1}, q=0..3
        if (n < N) {
            #pragma unroll
            for (int qq = 0; qq < 4; ++qq) {
                int c = p * 32 + 2 * (tx + 4 * qq);      // even column
                float lo, hi;
                unpack2(a[2 * qq],     lo, hi);
                float v0 = lo + hi;                      // wrong? a[2qq] is pair
                // a[2*qq] holds col c (two k-partials), a[2*qq+1] holds col c+1
                float lo1, hi1;
                unpack2(a[2 * qq + 1], lo1, hi1);
                float x0 = lo + hi   + cnt * g_bc[c]     + __ldg(b2 + c);
                float x1 = lo1 + hi1 + cnt * g_bc[c + 1] + __ldg(b2 + c + 1);
                (void)v0;
                x0 = (x0 >= 0.f) ? x0 : 0.01f * x0;
                x1 = (x1 >= 0.f) ? x1 : 0.01f * x1;
                *(float2*)(out + (size_t)n * OUTD + c) = make_float2(x0, x1);
            }
        }
    }
}

// ---------------- launch: pure kernel launches, no API calls -------------
extern "C" void kernel_launch(void* const* d_in, const int* in_sizes, int n_in,
                              void* d_out, int out_size) {
    // metadata order: msg, x_i, x_j, e_ij, index, num_nodes, W1, b1, W2, b2
    const float* msg   = (const float*)d_in[0];
    const int*   index = (const int*)  d_in[4];
    const float* W1    = (const float*)d_in[6];
    const float* b1    = (const float*)d_in[7];
    const float* W2    = (const float*)d_in[8];
    const float* b2    = (const float*)d_in[9];
    float* out = (float*)d_out;

    int E = in_sizes[4];
    int N = out_size / OUTD;
    if (N > NNODES) N = NNODES;

    wct_kernel<<<OUTD, OUTD>>>(W1, W2, b1);
    zero_kernel<<<2048, 256>>>();
    scatter_kernel<<<12500, 256>>>((const float4*)msg, index, E);
    final_kernel<<<(N + 63) / 64, 256>>>(b2, out, N);
}

// round 11
// speedup vs baseline: 1.9684x; 1.2809x over previous
#include <cuda_runtime.h>
#include <cstdint>

#define NNODES 50000
#define OUTD   128

// ---------------- device scratch (no allocations allowed) ----------------
__device__ float4 g_S4[NNODES * (OUTD / 4)];   // 25.6 MB accumulator S[N][128]
__device__ float  g_cnt[NNODES];               // per-node edge count (as float)
__device__ float4 g_Wp4[OUTD * OUTD / 4];      // Wc k-paired [k2][o][2]; 16B-aligned type
__device__ float  g_bc[OUTD];                  // W2 @ b1

// ---------------- f32x2 helpers ------------------------------------------
__device__ __forceinline__ void unpack2(unsigned long long v, float& x, float& y) {
    asm("mov.b64 {%0, %1}, %2;" : "=f"(x), "=f"(y) : "l"(v));
}
__device__ __forceinline__ void ffma2(unsigned long long& d,
                                      unsigned long long a,
                                      unsigned long long b) {
    asm("fma.rn.f32x2 %0, %1, %2, %0;" : "+l"(d) : "l"(a), "l"(b));
}
__device__ __forceinline__ void red4(float* dst, float4 v) {
    asm volatile("red.global.add.v4.f32 [%0], {%1, %2, %3, %4};"
                 :: "l"(dst), "f"(v.x), "f"(v.y), "f"(v.z), "f"(v.w)
                 : "memory");
}

// ---------------- prep: Wc = W2@W1 (k-paired) AND bc = W2@b1 -------------
// One block per output row o; 128 threads. (Passed in R10.)
__global__ void wct_kernel(const float* __restrict__ W1,   // [512, 128]
                           const float* __restrict__ W2,   // [128, 512]
                           const float* __restrict__ b1) {
    __shared__ float sb[128];
    const int o = blockIdx.x;
    const int k = threadIdx.x;
    const float* w2row = W2 + (size_t)o * 512;

    sb[k] = w2row[k] * __ldg(&b1[k])
          + w2row[k + 128] * __ldg(&b1[k + 128])
          + w2row[k + 256] * __ldg(&b1[k + 256])
          + w2row[k + 384] * __ldg(&b1[k + 384]);

    float acc = 0.f;
    #pragma unroll 8
    for (int h = 0; h < 512; ++h)
        acc += w2row[h] * W1[(size_t)h * OUTD + k];
    // k-paired store: float index (k/2)*256 + o*2 + (k&1)
    ((float*)g_Wp4)[(k >> 1) * 256 + o * 2 + (k & 1)] = acc;

    __syncthreads();
    if (k < 32) {
        float s = sb[k] + sb[k + 32] + sb[k + 64] + sb[k + 96];
        #pragma unroll
        for (int d = 16; d > 0; d >>= 1)
            s += __shfl_down_sync(0xffffffffu, s, d);
        if (k == 0) g_bc[o] = s;
    }
}

// ---------------- zero accumulators (required every graph replay) --------
__global__ void zero_kernel() {
    int i = blockIdx.x * blockDim.x + threadIdx.x;
    int stride = gridDim.x * blockDim.x;
    const int n4 = NNODES * (OUTD / 4);
    for (int j = i; j < n4; j += stride) g_S4[j] = make_float4(0.f, 0.f, 0.f, 0.f);
    for (int j = i; j < NNODES; j += stride) g_cnt[j] = 0.f;
}

// ---------------- scatter: S[index[e]] += msg[e]; cnt += 1 ---------------
// Warp per edge; LTS-transport bound; 94.6-95.4us across 4 runs. Verbatim.
__global__ void scatter_kernel(const float4* __restrict__ msg4,
                               const int* __restrict__ index, int E) {
    int lane  = threadIdx.x & 31;
    int warp  = (blockIdx.x * blockDim.x + threadIdx.x) >> 5;
    int nwarp = (gridDim.x * blockDim.x) >> 5;

    int e = warp;
    for (; e + 3 * nwarp < E; e += 4 * nwarp) {
        int e0 = e, e1 = e + nwarp, e2 = e + 2 * nwarp, e3 = e + 3 * nwarp;
        int n0 = __ldg(index + e0);
        int n1 = __ldg(index + e1);
        int n2 = __ldg(index + e2);
        int n3 = __ldg(index + e3);
        float4 v0 = __ldg(msg4 + (size_t)e0 * 32 + lane);
        float4 v1 = __ldg(msg4 + (size_t)e1 * 32 + lane);
        float4 v2 = __ldg(msg4 + (size_t)e2 * 32 + lane);
        float4 v3 = __ldg(msg4 + (size_t)e3 * 32 + lane);
        red4((float*)&g_S4[(size_t)n0 * 32 + lane], v0);
        red4((float*)&g_S4[(size_t)n1 * 32 + lane], v1);
        red4((float*)&g_S4[(size_t)n2 * 32 + lane], v2);
        red4((float*)&g_S4[(size_t)n3 * 32 + lane], v3);
        if (lane == 0) {
            atomicAdd(&g_cnt[n0], 1.0f);
            atomicAdd(&g_cnt[n1], 1.0f);
            atomicAdd(&g_cnt[n2], 1.0f);
            atomicAdd(&g_cnt[n3], 1.0f);
        }
    }
    for (; e < E; e += nwarp) {
        int n = __ldg(index + e);
        float4 v = __ldg(msg4 + (size_t)e * 32 + lane);
        red4((float*)&g_S4[(size_t)n * 32 + lane], v);
        if (lane == 0) atomicAdd(&g_cnt[n], 1.0f);
    }
}

// ---------------- final: out = leaky(S @ WcT + cnt*bc + b2) --------------
// 64 nodes/block, 256 threads, exactly 48 KB static smem.
// K processed in 2 chunks of 64; accumulators persist across chunks.
//   sS[64 r][64 f]: k-chunk of S, k-paired; pair k2 of row r stored at
//     r*64 + 2*((k2+r)&31) (rotation swizzle -> conflict-free LDS.64).
//   sW[32 k2][64 u]: k-chunk of W; unit u (float4 = k-pair x 2 cols) stored
//     at perm(u) = (u&3)*16 + (u>>2) so thread-strided reads are contiguous.
// Thread tile: 4 rows x 8 cols. Per k2: 4 LDS.64 + 4 LDS.128 -> 32 FFMA2.
__global__ void __launch_bounds__(256, 2) final_kernel(const float* __restrict__ b2,
                                                       float* __restrict__ out, int N) {
    __shared__ float  sS[64 * 64];     // 16384 B
    __shared__ float4 sW[32 * 64];     // 32768 B  (total = 48 KB exactly)

    const int t    = threadIdx.x;
    const int tx   = t & 15;           // col group: cols 8tx .. 8tx+7
    const int ty   = t >> 4;           // row group: rows 4ty .. 4ty+3
    const int row0 = blockIdx.x * 64;

    unsigned long long acc[4][8];      // [row][col offset]
    #pragma unroll
    for (int r = 0; r < 4; ++r)
        #pragma unroll
        for (int j = 0; j < 8; ++j) acc[r][j] = 0ull;

    #pragma unroll 1
    for (int kc = 0; kc < 2; ++kc) {
        __syncthreads();               // previous chunk's reads done

        // fill sS: 4 coalesced float4 loads per thread
        #pragma unroll
        for (int j = 0; j < 4; ++j) {
            int f = t + 256 * j;       // 0..1023
            int r = f >> 4;            // row 0..63
            int c4 = f & 15;           // float4 within k-chunk
            int n = row0 + r;
            float4 v = make_float4(0.f, 0.f, 0.f, 0.f);
            if (n < N) v = __ldg(&g_S4[(size_t)n * 32 + kc * 16 + c4]);
            int pa = (2 * c4 + r) & 31;
            int pb = (2 * c4 + 1 + r) & 31;
            *(float2*)&sS[r * 64 + 2 * pa] = make_float2(v.x, v.y);
            *(float2*)&sS[r * 64 + 2 * pb] = make_float2(v.z, v.w);
        }

        // fill sW: 8 float4 per thread, permuted store
        #pragma unroll
        for (int i = 0; i < 8; ++i) {
            int f = t + 256 * i;       // 0..2047
            int k2 = f >> 6;           // 0..31 (within chunk)
            int u  = f & 63;           // unit (2 cols) 0..63
            int pu = (u & 3) * 16 + (u >> 2);
            sW[k2 * 64 + pu] = g_Wp4[(size_t)(kc * 32 + k2) * 64 + u];
        }
        __syncthreads();

        #pragma unroll 2
        for (int k2 = 0; k2 < 32; ++k2) {
            // W: units tx*4+i land at perm = i*16 + tx (contiguous 256B/warp)
            float4 w0 = sW[k2 * 64 + 0 * 16 + tx];
            float4 w1 = sW[k2 * 64 + 1 * 16 + tx];
            float4 w2 = sW[k2 * 64 + 2 * 16 + tx];
            float4 w3 = sW[k2 * 64 + 3 * 16 + tx];
            // S: 4 rows, rotation-swizzled broadcast LDS.64
            unsigned long long s0 =
                *(const unsigned long long*)&sS[(4 * ty + 0) * 64 + 2 * ((k2 + 4 * ty + 0) & 31)];
            unsigned long long s1 =
                *(const unsigned long long*)&sS[(4 * ty + 1) * 64 + 2 * ((k2 + 4 * ty + 1) & 31)];
            unsigned long long s2 =
                *(const unsigned long long*)&sS[(4 * ty + 2) * 64 + 2 * ((k2 + 4 * ty + 2) & 31)];
            unsigned long long s3 =
                *(const unsigned long long*)&sS[(4 * ty + 3) * 64 + 2 * ((k2 + 4 * ty + 3) & 31)];

            const unsigned long long* q0 = (const unsigned long long*)&w0;
            const unsigned long long* q1 = (const unsigned long long*)&w1;
            const unsigned long long* q2 = (const unsigned long long*)&w2;
            const unsigned long long* q3 = (const unsigned long long*)&w3;

            ffma2(acc[0][0], s0, q0[0]); ffma2(acc[0][1], s0, q0[1]);
            ffma2(acc[0][2], s0, q1[0]); ffma2(acc[0][3], s0, q1[1]);
            ffma2(acc[0][4], s0, q2[0]); ffma2(acc[0][5], s0, q2[1]);
            ffma2(acc[0][6], s0, q3[0]); ffma2(acc[0][7], s0, q3[1]);

            ffma2(acc[1][0], s1, q0[0]); ffma2(acc[1][1], s1, q0[1]);
            ffma2(acc[1][2], s1, q1[0]); ffma2(acc[1][3], s1, q1[1]);
            ffma2(acc[1][4], s1, q2[0]); ffma2(acc[1][5], s1, q2[1]);
            ffma2(acc[1][6], s1, q3[0]); ffma2(acc[1][7], s1, q3[1]);

            ffma2(acc[2][0], s2, q0[0]); ffma2(acc[2][1], s2, q0[1]);
            ffma2(acc[2][2], s2, q1[0]); ffma2(acc[2][3], s2, q1[1]);
            ffma2(acc[2][4], s2, q2[0]); ffma2(acc[2][5], s2, q2[1]);
            ffma2(acc[2][6], s2, q3[0]); ffma2(acc[2][7], s2, q3[1]);

            ffma2(acc[3][0], s3, q0[0]); ffma2(acc[3][1], s3, q0[1]);
            ffma2(acc[3][2], s3, q1[0]); ffma2(acc[3][3], s3, q1[1]);
            ffma2(acc[3][4], s3, q2[0]); ffma2(acc[3][5], s3, q2[1]);
            ffma2(acc[3][6], s3, q3[0]); ffma2(acc[3][7], s3, q3[1]);
        }
    }

    // ---- epilogue: cols 8tx..8tx+7 per row; fold k-pairs, bias, leaky ----
    const int c0 = 8 * tx;
    float bcv[8], b2v[8];
    #pragma unroll
    for (int j = 0; j < 8; ++j) {
        bcv[j] = g_bc[c0 + j];
        b2v[j] = __ldg(b2 + c0 + j);
    }
    #pragma unroll
    for (int r = 0; r < 4; ++r) {
        int n = row0 + 4 * ty + r;
        if (n >= N) continue;
        float cnt = g_cnt[n];
        float res[8];
        #pragma unroll
        for (int j = 0; j < 8; ++j) {
            float lo, hi;
            unpack2(acc[r][j], lo, hi);
            float x = lo + hi + cnt * bcv[j] + b2v[j];
            res[j] = (x >= 0.f) ? x : 0.01f * x;
        }
        float4* o4 = (float4*)(out + (size_t)n * OUTD + c0);
        o4[0] = make_float4(res[0], res[1], res[2], res[3]);
        o4[1] = make_float4(res[4], res[5], res[6], res[7]);
    }
}

// ---------------- launch: pure kernel launches, no API calls -------------
extern "C" void kernel_launch(void* const* d_in, const int* in_sizes, int n_in,
                              void* d_out, int out_size) {
    // metadata order: msg, x_i, x_j, e_ij, index, num_nodes, W1, b1, W2, b2
    const float* msg   = (const float*)d_in[0];
    const int*   index = (const int*)  d_in[4];
    const float* W1    = (const float*)d_in[6];
    const float* b1    = (const float*)d_in[7];
    const float* W2    = (const float*)d_in[8];
    const float* b2    = (const float*)d_in[9];
    float* out = (float*)d_out;

    int E = in_sizes[4];
    int N = out_size / OUTD;
    if (N > NNODES) N = NNODES;

    wct_kernel<<<OUTD, OUTD>>>(W1, W2, b1);
    zero_kernel<<<2048, 256>>>();
    scatter_kernel<<<12500, 256>>>((const float4*)msg, index, E);
    final_kernel<<<(N + 63) / 64, 256>>>(b2, out, N);
}

// round 13
// speedup vs baseline: 2.0833x; 1.0584x over previous
#include <cuda_runtime.h>
#include <cstdint>

#define NNODES 50000
#define OUTD   128

// ---------------- device scratch (no allocations allowed) ----------------
__device__ float4 g_S4[NNODES * (OUTD / 4)];   // 25.6 MB accumulator S[N][128]
__device__ float  g_cnt[NNODES];               // per-node edge count (as float)
__device__ float4 g_Wp4[OUTD * OUTD / 4];      // Wc k-paired [k2][o][2]; 16B-aligned type
__device__ float  g_bc[OUTD];                  // W2 @ b1

// ---------------- f32x2 helpers ------------------------------------------
__device__ __forceinline__ void unpack2(unsigned long long v, float& x, float& y) {
    asm("mov.b64 {%0, %1}, %2;" : "=f"(x), "=f"(y) : "l"(v));
}
__device__ __forceinline__ void ffma2(unsigned long long& d,
                                      unsigned long long a,
                                      unsigned long long b) {
    asm("fma.rn.f32x2 %0, %1, %2, %0;" : "+l"(d) : "l"(a), "l"(b));
}
__device__ __forceinline__ void red4(float* dst, float4 v) {
    asm volatile("red.global.add.v4.f32 [%0], {%1, %2, %3, %4};"
                 :: "l"(dst), "f"(v.x), "f"(v.y), "f"(v.z), "f"(v.w)
                 : "memory");
}

// ---------------- prep: Wc = W2@W1 (k-paired) AND bc = W2@b1 -------------
// One block per output row o; 128 threads. (Passed R10/R11.)
__global__ void wct_kernel(const float* __restrict__ W1,   // [512, 128]
                           const float* __restrict__ W2,   // [128, 512]
                           const float* __restrict__ b1) {
    __shared__ float sb[128];
    const int o = blockIdx.x;
    const int k = threadIdx.x;
    const float* w2row = W2 + (size_t)o * 512;

    sb[k] = w2row[k] * __ldg(&b1[k])
          + w2row[k + 128] * __ldg(&b1[k + 128])
          + w2row[k + 256] * __ldg(&b1[k + 256])
          + w2row[k + 384] * __ldg(&b1[k + 384]);

    float acc = 0.f;
    #pragma unroll 8
    for (int h = 0; h < 512; ++h)
        acc += w2row[h] * W1[(size_t)h * OUTD + k];
    // k-paired store: float index (k/2)*256 + o*2 + (k&1)
    ((float*)g_Wp4)[(k >> 1) * 256 + o * 2 + (k & 1)] = acc;

    __syncthreads();
    if (k < 32) {
        float s = sb[k] + sb[k + 32] + sb[k + 64] + sb[k + 96];
        #pragma unroll
        for (int d = 16; d > 0; d >>= 1)
            s += __shfl_down_sync(0xffffffffu, s, d);
        if (k == 0) g_bc[o] = s;
    }
}

// ---------------- zero accumulators (required every graph replay) --------
__global__ void zero_kernel() {
    int i = blockIdx.x * blockDim.x + threadIdx.x;
    int stride = gridDim.x * blockDim.x;
    const int n4 = NNODES * (OUTD / 4);
    for (int j = i; j < n4; j += stride) g_S4[j] = make_float4(0.f, 0.f, 0.f, 0.f);
    for (int j = i; j < NNODES; j += stride) g_cnt[j] = 0.f;
}

// ---------------- scatter: S[index[e]] += msg[e]; cnt += 1 ---------------
// Warp per edge; DRAM/LTS bound; 94.6-95.4us across 5 runs. Verbatim.
__global__ void scatter_kernel(const float4* __restrict__ msg4,
                               const int* __restrict__ index, int E) {
    int lane  = threadIdx.x & 31;
    int warp  = (blockIdx.x * blockDim.x + threadIdx.x) >> 5;
    int nwarp = (gridDim.x * blockDim.x) >> 5;

    int e = warp;
    for (; e + 3 * nwarp < E; e += 4 * nwarp) {
        int e0 = e, e1 = e + nwarp, e2 = e + 2 * nwarp, e3 = e + 3 * nwarp;
        int n0 = __ldg(index + e0);
        int n1 = __ldg(index + e1);
        int n2 = __ldg(index + e2);
        int n3 = __ldg(index + e3);
        float4 v0 = __ldg(msg4 + (size_t)e0 * 32 + lane);
        float4 v1 = __ldg(msg4 + (size_t)e1 * 32 + lane);
        float4 v2 = __ldg(msg4 + (size_t)e2 * 32 + lane);
        float4 v3 = __ldg(msg4 + (size_t)e3 * 32 + lane);
        red4((float*)&g_S4[(size_t)n0 * 32 + lane], v0);
        red4((float*)&g_S4[(size_t)n1 * 32 + lane], v1);
        red4((float*)&g_S4[(size_t)n2 * 32 + lane], v2);
        red4((float*)&g_S4[(size_t)n3 * 32 + lane], v3);
        if (lane == 0) {
            atomicAdd(&g_cnt[n0], 1.0f);
            atomicAdd(&g_cnt[n1], 1.0f);
            atomicAdd(&g_cnt[n2], 1.0f);
            atomicAdd(&g_cnt[n3], 1.0f);
        }
    }
    for (; e < E; e += nwarp) {
        int n = __ldg(index + e);
        float4 v = __ldg(msg4 + (size_t)e * 32 + lane);
        red4((float*)&g_S4[(size_t)n * 32 + lane], v);
        if (lane == 0) atomicAdd(&g_cnt[n], 1.0f);
    }
}

// ---------------- final: out = leaky(S @ WcT + cnt*bc + b2) --------------
// 64 nodes/block, 256 threads, 49152 B static smem EXACTLY (0xc000).
// K in 2 chunks of 64; accumulators persist across chunks.
//   sS[64][64] UNPADDED: S read addr = row*64 + 2*k2, pure pointer increment,
//     no per-iteration swizzle ALU. One LDS.64 touches only 2 distinct
//     addresses per warp (ty spans 2 rows/warp); 2 broadcast phases = the
//     256B structural floor of LDS.64 -> effectively conflict-free.
//   sW[32 k2][64 u]: unit u stored at perm(u)=(u&3)*16+(u>>2) so the 4
//     LDS.128 per k2 read contiguous 256B per warp.
// Thread tile: 4 rows x 8 cols. Per k2: 4 LDS.64 + 4 LDS.128 -> 32 FFMA2.
__global__ void __launch_bounds__(256, 2) final_kernel(const float* __restrict__ b2,
                                                       float* __restrict__ out, int N) {
    __shared__ __align__(16) float sS[64 * 64];   // 16384 B
    __shared__ float4 sW[32 * 64];                // 32768 B (total 49152 B)

    const int t    = threadIdx.x;
    const int tx   = t & 15;           // col group: cols 8tx .. 8tx+7
    const int ty   = t >> 4;           // row group: rows 4ty .. 4ty+3
    const int row0 = blockIdx.x * 64;

    unsigned long long acc[4][8];      // [row][col offset]
    #pragma unroll
    for (int r = 0; r < 4; ++r)
        #pragma unroll
        for (int j = 0; j < 8; ++j) acc[r][j] = 0ull;

    const float* sR0 = sS + (4 * ty + 0) * 64;
    const float* sR1 = sS + (4 * ty + 1) * 64;
    const float* sR2 = sS + (4 * ty + 2) * 64;
    const float* sR3 = sS + (4 * ty + 3) * 64;

    #pragma unroll 1
    for (int kc = 0; kc < 2; ++kc) {
        __syncthreads();               // previous chunk's reads done

        // fill sS: 4 coalesced float4 loads, aligned STS.128 (no swizzle)
        #pragma unroll
        for (int j = 0; j < 4; ++j) {
            int f = t + 256 * j;       // 0..1023
            int r = f >> 4;            // row 0..63
            int c4 = f & 15;           // float4 within k-chunk
            int n = row0 + r;
            float4 v = make_float4(0.f, 0.f, 0.f, 0.f);
            if (n < N) v = __ldg(&g_S4[(size_t)n * 32 + kc * 16 + c4]);
            *(float4*)&sS[r * 64 + 4 * c4] = v;
        }

        // fill sW: 8 float4 per thread, permuted store
        #pragma unroll
        for (int i = 0; i < 8; ++i) {
            int f = t + 256 * i;       // 0..2047
            int k2 = f >> 6;           // 0..31 (within chunk)
            int u  = f & 63;           // unit (k-pair x 2 cols)
            int pu = (u & 3) * 16 + (u >> 2);
            sW[k2 * 64 + pu] = g_Wp4[(size_t)(kc * 32 + k2) * 64 + u];
        }
        __syncthreads();

        #pragma unroll 2
        for (int k2 = 0; k2 < 32; ++k2) {
            float4 w0 = sW[k2 * 64 + 0 * 16 + tx];
            float4 w1 = sW[k2 * 64 + 1 * 16 + tx];
            float4 w2 = sW[k2 * 64 + 2 * 16 + tx];
            float4 w3 = sW[k2 * 64 + 3 * 16 + tx];
            unsigned long long s0 = *(const unsigned long long*)(sR0 + 2 * k2);
            unsigned long long s1 = *(const unsigned long long*)(sR1 + 2 * k2);
            unsigned long long s2 = *(const unsigned long long*)(sR2 + 2 * k2);
            unsigned long long s3 = *(const unsigned long long*)(sR3 + 2 * k2);

            const unsigned long long* q0 = (const unsigned long long*)&w0;
            const unsigned long long* q1 = (const unsigned long long*)&w1;
            const unsigned long long* q2 = (const unsigned long long*)&w2;
            const unsigned long long* q3 = (const unsigned long long*)&w3;

            ffma2(acc[0][0], s0, q0[0]); ffma2(acc[0][1], s0, q0[1]);
            ffma2(acc[0][2], s0, q1[0]); ffma2(acc[0][3], s0, q1[1]);
            ffma2(acc[0][4], s0, q2[0]); ffma2(acc[0][5], s0, q2[1]);
            ffma2(acc[0][6], s0, q3[0]); ffma2(acc[0][7], s0, q3[1]);

            ffma2(acc[1][0], s1, q0[0]); ffma2(acc[1][1], s1, q0[1]);
            ffma2(acc[1][2], s1, q1[0]); ffma2(acc[1][3], s1, q1[1]);
            ffma2(acc[1][4], s1, q2[0]); ffma2(acc[1][5], s1, q2[1]);
            ffma2(acc[1][6], s1, q3[0]); ffma2(acc[1][7], s1, q3[1]);

            ffma2(acc[2][0], s2, q0[0]); ffma2(acc[2][1], s2, q0[1]);
            ffma2(acc[2][2], s2, q1[0]); ffma2(acc[2][3], s2, q1[1]);
            ffma2(acc[2][4], s2, q2[0]); ffma2(acc[2][5], s2, q2[1]);
            ffma2(acc[2][6], s2, q3[0]); ffma2(acc[2][7], s2, q3[1]);

            ffma2(acc[3][0], s3, q0[0]); ffma2(acc[3][1], s3, q0[1]);
            ffma2(acc[3][2], s3, q1[0]); ffma2(acc[3][3], s3, q1[1]);
            ffma2(acc[3][4], s3, q2[0]); ffma2(acc[3][5], s3, q2[1]);
            ffma2(acc[3][6], s3, q3[0]); ffma2(acc[3][7], s3, q3[1]);
        }
    }

    // ---- epilogue: cols 8tx..8tx+7 per row; fold k-pairs, bias, leaky ----
    const int c0 = 8 * tx;
    float bcv[8], b2v[8];
    #pragma unroll
    for (int j = 0; j < 8; ++j) {
        bcv[j] = g_bc[c0 + j];
        b2v[j] = __ldg(b2 + c0 + j);
    }
    #pragma unroll
    for (int r = 0; r < 4; ++r) {
        int n = row0 + 4 * ty + r;
        if (n >= N) continue;
        float cnt = g_cnt[n];
        float res[8];
        #pragma unroll
        for (int j = 0; j < 8; ++j) {
            float lo, hi;
            unpack2(acc[r][j], lo, hi);
            float x = lo + hi + cnt * bcv[j] + b2v[j];
            res[j] = (x >= 0.f) ? x : 0.01f * x;
        }
        float4* o4 = (float4*)(out + (size_t)n * OUTD + c0);
        o4[0] = make_float4(res[0], res[1], res[2], res[3]);
        o4[1] = make_float4(res[4], res[5], res[6], res[7]);
    }
}

// ---------------- launch: pure kernel launches, no API calls -------------
extern "C" void kernel_launch(void* const* d_in, const int* in_sizes, int n_in,
                              void* d_out, int out_size) {
    // metadata order: msg, x_i, x_j, e_ij, index, num_nodes, W1, b1, W2, b2
    const float* msg   = (const float*)d_in[0];
    const int*   index = (const int*)  d_in[4];
    const float* W1    = (const float*)d_in[6];
    const float* b1    = (const float*)d_in[7];
    const float* W2    = (const float*)d_in[8];
    const float* b2    = (const float*)d_in[9];
    float* out = (float*)d_out;

    int E = in_sizes[4];
    int N = out_size / OUTD;
    if (N > NNODES) N = NNODES;

    wct_kernel<<<OUTD, OUTD>>>(W1, W2, b1);
    zero_kernel<<<2048, 256>>>();
    scatter_kernel<<<12500, 256>>>((const float4*)msg, index, E);
    final_kernel<<<(N + 63) / 64, 256>>>(b2, out, N);
}

// round 14
// speedup vs baseline: 2.0965x; 1.0063x over previous
#include <cuda_runtime.h>
#include <cstdint>

#define NNODES 50000
#define OUTD   128

// ---------------- device scratch (no allocations allowed) ----------------
__device__ float4 g_S4[NNODES * (OUTD / 4)];   // 25.6 MB accumulator S[N][128]
__device__ float  g_cnt[NNODES];               // per-node edge count (as float)
__device__ float4 g_Wp4[OUTD * OUTD / 4];      // Wc k-paired [k2][o][2]; 16B-aligned type
__device__ float  g_bc[OUTD];                  // W2 @ b1

// ---------------- f32x2 helpers ------------------------------------------
__device__ __forceinline__ void unpack2(unsigned long long v, float& x, float& y) {
    asm("mov.b64 {%0, %1}, %2;" : "=f"(x), "=f"(y) : "l"(v));
}
__device__ __forceinline__ void ffma2(unsigned long long& d,
                                      unsigned long long a,
                                      unsigned long long b) {
    asm("fma.rn.f32x2 %0, %1, %2, %0;" : "+l"(d) : "l"(a), "l"(b));
}
__device__ __forceinline__ void red4(float* dst, float4 v) {
    asm volatile("red.global.add.v4.f32 [%0], {%1, %2, %3, %4};"
                 :: "l"(dst), "f"(v.x), "f"(v.y), "f"(v.z), "f"(v.w)
                 : "memory");
}

// ------- merged prep + zero: one launch, overlapping work kinds ----------
// Blocks 0..127 (128 thr): Wc = W2@W1 k-paired + bc = W2@b1 (latency-bound).
// Blocks 128..  (256 thr-worth of grid-stride): zero g_S4/g_cnt (BW-bound).
__global__ void __launch_bounds__(256) prepzero_kernel(const float* __restrict__ W1,
                                                       const float* __restrict__ W2,
                                                       const float* __restrict__ b1) {
    if (blockIdx.x < 128) {
        __shared__ float sb[128];
        const int o = blockIdx.x;
        const int k = threadIdx.x;
        if (k >= 128) return;
        const float* w2row = W2 + (size_t)o * 512;

        sb[k] = w2row[k] * __ldg(&b1[k])
              + w2row[k + 128] * __ldg(&b1[k + 128])
              + w2row[k + 256] * __ldg(&b1[k + 256])
              + w2row[k + 384] * __ldg(&b1[k + 384]);

        float acc = 0.f;
        #pragma unroll 8
        for (int h = 0; h < 512; ++h)
            acc += w2row[h] * W1[(size_t)h * OUTD + k];
        // k-paired store: float index (k/2)*256 + o*2 + (k&1)
        ((float*)g_Wp4)[(k >> 1) * 256 + o * 2 + (k & 1)] = acc;

        __syncthreads();
        if (k < 32) {
            float s = sb[k] + sb[k + 32] + sb[k + 64] + sb[k + 96];
            #pragma unroll
            for (int d = 16; d > 0; d >>= 1)
                s += __shfl_down_sync(0xffffffffu, s, d);
            if (k == 0) g_bc[o] = s;
        }
    } else {
        int i = (blockIdx.x - 128) * blockDim.x + threadIdx.x;
        int stride = (gridDim.x - 128) * blockDim.x;
        const int n4 = NNODES * (OUTD / 4);
        for (int j = i; j < n4; j += stride)
            g_S4[j] = make_float4(0.f, 0.f, 0.f, 0.f);
        for (int j = i; j < NNODES; j += stride) g_cnt[j] = 0.f;
    }
}

// ---------------- scatter: S[index[e]] += msg[e]; cnt += 1 ---------------
// Warp per edge; DRAM/LTS bound; 94.6-95.4us across 6 runs. Verbatim.
__global__ void scatter_kernel(const float4* __restrict__ msg4,
                               const int* __restrict__ index, int E) {
    int lane  = threadIdx.x & 31;
    int warp  = (blockIdx.x * blockDim.x + threadIdx.x) >> 5;
    int nwarp = (gridDim.x * blockDim.x) >> 5;

    int e = warp;
    for (; e + 3 * nwarp < E; e += 4 * nwarp) {
        int e0 = e, e1 = e + nwarp, e2 = e + 2 * nwarp, e3 = e + 3 * nwarp;
        int n0 = __ldg(index + e0);
        int n1 = __ldg(index + e1);
        int n2 = __ldg(index + e2);
        int n3 = __ldg(index + e3);
        float4 v0 = __ldg(msg4 + (size_t)e0 * 32 + lane);
        float4 v1 = __ldg(msg4 + (size_t)e1 * 32 + lane);
        float4 v2 = __ldg(msg4 + (size_t)e2 * 32 + lane);
        float4 v3 = __ldg(msg4 + (size_t)e3 * 32 + lane);
        red4((float*)&g_S4[(size_t)n0 * 32 + lane], v0);
        red4((float*)&g_S4[(size_t)n1 * 32 + lane], v1);
        red4((float*)&g_S4[(size_t)n2 * 32 + lane], v2);
        red4((float*)&g_S4[(size_t)n3 * 32 + lane], v3);
        if (lane == 0) {
            atomicAdd(&g_cnt[n0], 1.0f);
            atomicAdd(&g_cnt[n1], 1.0f);
            atomicAdd(&g_cnt[n2], 1.0f);
            atomicAdd(&g_cnt[n3], 1.0f);
        }
    }
    for (; e < E; e += nwarp) {
        int n = __ldg(index + e);
        float4 v = __ldg(msg4 + (size_t)e * 32 + lane);
        red4((float*)&g_S4[(size_t)n * 32 + lane], v);
        if (lane == 0) atomicAdd(&g_cnt[n], 1.0f);
    }
}

// ---------------- final: out = leaky(S @ WcT + cnt*bc + b2) --------------
// 64 nodes/block, 256 threads, 49152 B static smem exactly.
// K in 2 chunks of 64; accumulators persist. Inner loop unrolls 2 k-pairs:
// one LDS.128 per S row covers both pairs -> 12 LDS per 2-k2 (was 16).
//   sS[64][64] unpadded: S addr = row*64 + 2*k2 (pure increment; even k2 ->
//     16B aligned for LDS.128).
//   sW[32 k2][64 u]: unit u at perm(u)=(u&3)*16+(u>>2): LDS.128 contiguous.
// Thread tile: 4 rows x 8 cols -> 64 FFMA2 per 2-k2.
__global__ void __launch_bounds__(256, 2) final_kernel(const float* __restrict__ b2,
                                                       float* __restrict__ out, int N) {
    __shared__ __align__(16) float sS[64 * 64];   // 16384 B
    __shared__ float4 sW[32 * 64];                // 32768 B (total 49152 B)

    const int t    = threadIdx.x;
    const int tx   = t & 15;           // col group: cols 8tx .. 8tx+7
    const int ty   = t >> 4;           // row group: rows 4ty .. 4ty+3
    const int row0 = blockIdx.x * 64;

    unsigned long long acc[4][8];      // [row][col offset]
    #pragma unroll
    for (int r = 0; r < 4; ++r)
        #pragma unroll
        for (int j = 0; j < 8; ++j) acc[r][j] = 0ull;

    const float* sR0 = sS + (4 * ty + 0) * 64;
    const float* sR1 = sS + (4 * ty + 1) * 64;
    const float* sR2 = sS + (4 * ty + 2) * 64;
    const float* sR3 = sS + (4 * ty + 3) * 64;

    #pragma unroll 1
    for (int kc = 0; kc < 2; ++kc) {
        __syncthreads();               // previous chunk's reads done

        // fill sS: 4 coalesced float4 loads, aligned STS.128
        #pragma unroll
        for (int j = 0; j < 4; ++j) {
            int f = t + 256 * j;       // 0..1023
            int r = f >> 4;            // row 0..63
            int c4 = f & 15;           // float4 within k-chunk
            int n = row0 + r;
            float4 v = make_float4(0.f, 0.f, 0.f, 0.f);
            if (n < N) v = __ldg(&g_S4[(size_t)n * 32 + kc * 16 + c4]);
            *(float4*)&sS[r * 64 + 4 * c4] = v;
        }

        // fill sW: 8 float4 per thread, permuted store
        #pragma unroll
        for (int i = 0; i < 8; ++i) {
            int f = t + 256 * i;       // 0..2047
            int k2 = f >> 6;           // 0..31 (within chunk)
            int u  = f & 63;           // unit (k-pair x 2 cols)
            int pu = (u & 3) * 16 + (u >> 2);
            sW[k2 * 64 + pu] = g_Wp4[(size_t)(kc * 32 + k2) * 64 + u];
        }
        __syncthreads();

        #pragma unroll 2
        for (int k2 = 0; k2 < 32; k2 += 2) {
            // W for k2 and k2+1: 8 LDS.128, contiguous 256B per warp each
            float4 wa0 = sW[(k2 + 0) * 64 + 0 * 16 + tx];
            float4 wa1 = sW[(k2 + 0) * 64 + 1 * 16 + tx];
            float4 wa2 = sW[(k2 + 0) * 64 + 2 * 16 + tx];
            float4 wa3 = sW[(k2 + 0) * 64 + 3 * 16 + tx];
            float4 wb0 = sW[(k2 + 1) * 64 + 0 * 16 + tx];
            float4 wb1 = sW[(k2 + 1) * 64 + 1 * 16 + tx];
            float4 wb2 = sW[(k2 + 1) * 64 + 2 * 16 + tx];
            float4 wb3 = sW[(k2 + 1) * 64 + 3 * 16 + tx];
            // S: one LDS.128 per row covers pairs k2 (x,y) and k2+1 (z,w)
            float4 sv0 = *(const float4*)(sR0 + 2 * k2);
            float4 sv1 = *(const float4*)(sR1 + 2 * k2);
            float4 sv2 = *(const float4*)(sR2 + 2 * k2);
            float4 sv3 = *(const float4*)(sR3 + 2 * k2);

            const unsigned long long* qa0 = (const unsigned long long*)&wa0;
            const unsigned long long* qa1 = (const unsigned long long*)&wa1;
            const unsigned long long* qa2 = (const unsigned long long*)&wa2;
            const unsigned long long* qa3 = (const unsigned long long*)&wa3;
            const unsigned long long* qb0 = (const unsigned long long*)&wb0;
            const unsigned long long* qb1 = (const unsigned long long*)&wb1;
            const unsigned long long* qb2 = (const unsigned long long*)&wb2;
            const unsigned long long* qb3 = (const unsigned long long*)&wb3;

            #define ROW_STEP(r, sv)                                              \
            {                                                                    \
                const unsigned long long* sp = (const unsigned long long*)&(sv); \
                unsigned long long slo = sp[0], shi = sp[1];                     \
                ffma2(acc[r][0], slo, qa0[0]); ffma2(acc[r][1], slo, qa0[1]);    \
                ffma2(acc[r][2], slo, qa1[0]); ffma2(acc[r][3], slo, qa1[1]);    \
                ffma2(acc[r][4], slo, qa2[0]); ffma2(acc[r][5], slo, qa2[1]);    \
                ffma2(acc[r][6], slo, qa3[0]); ffma2(acc[r][7], slo, qa3[1]);    \
                ffma2(acc[r][0], shi, qb0[0]); ffma2(acc[r][1], shi, qb0[1]);    \
                ffma2(acc[r][2], shi, qb1[0]); ffma2(acc[r][3], shi, qb1[1]);    \
                ffma2(acc[r][4], shi, qb2[0]); ffma2(acc[r][5], shi, qb2[1]);    \
                ffma2(acc[r][6], shi, qb3[0]); ffma2(acc[r][7], shi, qb3[1]);    \
            }
            ROW_STEP(0, sv0)
            ROW_STEP(1, sv1)
            ROW_STEP(2, sv2)
            ROW_STEP(3, sv3)
            #undef ROW_STEP
        }
    }

    // ---- epilogue: cols 8tx..8tx+7 per row; fold k-pairs, bias, leaky ----
    const int c0 = 8 * tx;
    float bcv[8], b2v[8];
    #pragma unroll
    for (int j = 0; j < 8; ++j) {
        bcv[j] = g_bc[c0 + j];
        b2v[j] = __ldg(b2 + c0 + j);
    }
    #pragma unroll
    for (int r = 0; r < 4; ++r) {
        int n = row0 + 4 * ty + r;
        if (n >= N) continue;
        float cnt = g_cnt[n];
        float res[8];
        #pragma unroll
        for (int j = 0; j < 8; ++j) {
            float lo, hi;
            unpack2(acc[r][j], lo, hi);
            float x = lo + hi + cnt * bcv[j] + b2v[j];
            res[j] = (x >= 0.f) ? x : 0.01f * x;
        }
        float4* o4 = (float4*)(out + (size_t)n * OUTD + c0);
        o4[0] = make_float4(res[0], res[1], res[2], res[3]);
        o4[1] = make_float4(res[4], res[5], res[6], res[7]);
    }
}

// ---------------- launch: pure kernel launches, no API calls -------------
extern "C" void kernel_launch(void* const* d_in, const int* in_sizes, int n_in,
                              void* d_out, int out_size) {
    // metadata order: msg, x_i, x_j, e_ij, index, num_nodes, W1, b1, W2, b2
    const float* msg   = (const float*)d_in[0];
    const int*   index = (const int*)  d_in[4];
    const float* W1    = (const float*)d_in[6];
    const float* b1    = (const float*)d_in[7];
    const float* W2    = (const float*)d_in[8];
    const float* b2    = (const float*)d_in[9];
    float* out = (float*)d_out;

    int E = in_sizes[4];
    int N = out_size / OUTD;
    if (N > NNODES) N = NNODES;

    prepzero_kernel<<<128 + 2048, 256>>>(W1, W2, b1);
    scatter_kernel<<<12500, 256>>>((const float4*)msg, index, E);
    final_kernel<<<(N + 63) / 64, 256>>>(b2, out, N);
}